// round 11
// baseline (speedup 1.0000x reference)
#include <cuda_runtime.h>
#include <cstdint>
#include <cstddef>

// ---------------------------------------------------------------------------
// Problem constants
// ---------------------------------------------------------------------------
#define NN   100000
#define NE   100000
#define DIM  768
#define DIM2 1536
#define NT   5
#define LN_EPS 1e-5f

// Tiling: CTA 128x128, 8 warps in 2x4, warp tile 64x32, BK=32, 3 stages.
// LDA=32 + XOR swizzle: conflict-free LDS.128, 32KB/stage.
// 256 threads, <=128 regs -> 2 CTAs/SM = 16 warps/SM.
#define BM 128
#define BN 128
#define BK 32
#define THREADS 256
#define LDA 32
#define A_STG_BYTES (BM * LDA * 4)          // 16384
#define B_STG_BYTES (BN * LDA * 4)          // 16384
#define STG_BYTES   (A_STG_BYTES + B_STG_BYTES)  // 32768
#define SM_IDX   0              // 1024 bytes: s_src(512) + s_tgt(512)
#define SM_TILES 1024
#define SMEM_SZ  (SM_TILES + 3 * STG_BYTES)      // 99328

// ---------------------------------------------------------------------------
// Device scratch. tf32 copies stored K-PERMUTED: in each 16-float K-group,
// phys[4t+j] = logical[t+4j]; fragment elements for two k-steps contiguous.
// ---------------------------------------------------------------------------
__device__ float g_agg[(size_t)NN * DIM];
__device__ float g_xtf[(size_t)NN * DIM];
__device__ float g_wmtf[(size_t)NT * DIM * DIM];
__device__ float g_wutf[(size_t)DIM * DIM2];
__device__ int   g_bucket[NT][NE];
__device__ int   g_count[NT];

// ---------------------------------------------------------------------------
// Helpers
// ---------------------------------------------------------------------------
__device__ __forceinline__ uint32_t smem_u32(const void* p) {
    uint32_t a;
    asm("{ .reg .u64 t; cvta.to.shared.u64 t, %1; cvt.u32.u64 %0, t; }"
        : "=r"(a) : "l"(p));
    return a;
}

__device__ __forceinline__ void cpa16(uint32_t s, const void* g) {
    asm volatile("cp.async.cg.shared.global [%0], [%1], 16;"
                 :: "r"(s), "l"(g) : "memory");
}
__device__ __forceinline__ void cpa_commit() {
    asm volatile("cp.async.commit_group;" ::: "memory");
}
__device__ __forceinline__ void cpa_wait1() {
    asm volatile("cp.async.wait_group 1;" ::: "memory");
}
__device__ __forceinline__ void cpa_wait0() {
    asm volatile("cp.async.wait_group 0;" ::: "memory");
}

__device__ __forceinline__ float f2tf_f(float x) {
    unsigned r;
    asm("cvt.rna.tf32.f32 %0, %1;" : "=r"(r) : "f"(x));
    return __uint_as_float(r);
}

__device__ __forceinline__ void mma8(float& c0, float& c1, float& c2, float& c3,
                                     unsigned a0, unsigned a1, unsigned a2, unsigned a3,
                                     unsigned b0, unsigned b1) {
    asm volatile(
        "mma.sync.aligned.m16n8k8.row.col.f32.tf32.tf32.f32 "
        "{%0,%1,%2,%3}, {%4,%5,%6,%7}, {%8,%9}, {%0,%1,%2,%3};\n"
        : "+f"(c0), "+f"(c1), "+f"(c2), "+f"(c3)
        : "r"(a0), "r"(a1), "r"(a2), "r"(a3), "r"(b0), "r"(b1));
}

// vector reduction: one 8-byte atomic add (sm_90+)
__device__ __forceinline__ void red2(float* addr, float x, float y) {
    asm volatile("red.global.add.v2.f32 [%0], {%1, %2};"
                 :: "l"(addr), "f"(x), "f"(y) : "memory");
}

// one BK=32 slice on a 64x32 warp tile: 2 k-pairs, swizzled LDS.128 frags.
__device__ __forceinline__ void compute_stage(const unsigned* __restrict__ As,
                                              const unsigned* __restrict__ Bs,
                                              float c[4][4][4],
                                              int wm, int wn, int g, int tg) {
    int xorv = (g & 1) << 2;
#pragma unroll
    for (int kp = 0; kp < 2; ++kp) {
        int cf = ((kp * 4 + tg) ^ xorv) * 4;   // float offset within 32-float row
        uint4 a[4][2], b[4];
#pragma unroll
        for (int im = 0; im < 4; ++im) {
            int mb = wm * 64 + im * 16;
            a[im][0] = *reinterpret_cast<const uint4*>(&As[(mb + g) * LDA + cf]);
            a[im][1] = *reinterpret_cast<const uint4*>(&As[(mb + g + 8) * LDA + cf]);
        }
#pragma unroll
        for (int in_ = 0; in_ < 4; ++in_) {
            int nb = wn * 32 + in_ * 8 + g;
            b[in_] = *reinterpret_cast<const uint4*>(&Bs[nb * LDA + cf]);
        }
#pragma unroll
        for (int im = 0; im < 4; ++im)
#pragma unroll
            for (int in_ = 0; in_ < 4; ++in_) {
                mma8(c[im][in_][0], c[im][in_][1], c[im][in_][2], c[im][in_][3],
                     a[im][0].x, a[im][1].x, a[im][0].y, a[im][1].y,
                     b[in_].x, b[in_].y);
                mma8(c[im][in_][0], c[im][in_][1], c[im][in_][2], c[im][in_][3],
                     a[im][0].z, a[im][1].z, a[im][0].w, a[im][1].w,
                     b[in_].z, b[in_].w);
            }
    }
}

// ---------------------------------------------------------------------------
// K0 / K1: init + bucket
// ---------------------------------------------------------------------------
__global__ void k_init() {
    size_t idx = (size_t)blockIdx.x * blockDim.x + threadIdx.x;
    if (idx < NT) g_count[idx] = 0;
    float4* p = reinterpret_cast<float4*>(g_agg);
    size_t n4 = (size_t)NN * DIM / 4;
    size_t stride = (size_t)gridDim.x * blockDim.x;
    for (size_t i = idx; i < n4; i += stride) p[i] = make_float4(0.f, 0.f, 0.f, 0.f);
}

__global__ void k_bucket(const int* __restrict__ etype) {
    int e = blockIdx.x * blockDim.x + threadIdx.x;
    if (e < NE) {
        int t = etype[e];
        int pos = atomicAdd(&g_count[t], 1);
        g_bucket[t][pos] = e;
    }
}

// tf32-round + K-permute one 16-float group
__device__ __forceinline__ void cvtp_group(const float* src, float* dst, size_t i) {
    const float4* s = reinterpret_cast<const float4*>(src) + i * 4;
    float4 v0 = s[0], v1 = s[1], v2 = s[2], v3 = s[3];
    float4* d = reinterpret_cast<float4*>(dst) + i * 4;
    float4 o;
    o.x = f2tf_f(v0.x); o.y = f2tf_f(v1.x); o.z = f2tf_f(v2.x); o.w = f2tf_f(v3.x);
    d[0] = o;
    o.x = f2tf_f(v0.y); o.y = f2tf_f(v1.y); o.z = f2tf_f(v2.y); o.w = f2tf_f(v3.y);
    d[1] = o;
    o.x = f2tf_f(v0.z); o.y = f2tf_f(v1.z); o.z = f2tf_f(v2.z); o.w = f2tf_f(v3.z);
    d[2] = o;
    o.x = f2tf_f(v0.w); o.y = f2tf_f(v1.w); o.z = f2tf_f(v2.w); o.w = f2tf_f(v3.w);
    d[3] = o;
}

__global__ void k_cvtp(const float* src, float* dst, size_t ngroups) {
    size_t idx = (size_t)blockIdx.x * blockDim.x + threadIdx.x;
    size_t stride = (size_t)gridDim.x * blockDim.x;
    for (size_t i = idx; i < ngroups; i += stride) cvtp_group(src, dst, i);
}

__global__ void k_cvtp3(const float* s0, float* d0, size_t n0,
                        const float* s1, float* d1, size_t n1,
                        const float* s2, float* d2, size_t n2) {
    size_t idx = (size_t)blockIdx.x * blockDim.x + threadIdx.x;
    size_t stride = (size_t)gridDim.x * blockDim.x;
    size_t total = n0 + n1 + n2;
    for (size_t i = idx; i < total; i += stride) {
        if (i < n0) cvtp_group(s0, d0, i);
        else if (i < n0 + n1) cvtp_group(s1, d1, i - n0);
        else cvtp_group(s2, d2, i - n0 - n1);
    }
}

// ---------------------------------------------------------------------------
// K2: per-type gather-GEMM, vector-atomic scatter-add into g_agg
//     grid (DIM/BN, ceil(NE/BM), NT), 256 threads, 2 CTA/SM
// ---------------------------------------------------------------------------
__global__ __launch_bounds__(THREADS, 2) void k_msg(const float* __restrict__ bm,
                                                    const int*   __restrict__ eidx) {
    int t = blockIdx.z;
    int cnt = g_count[t];
    int m0 = blockIdx.y * BM;
    if (m0 >= cnt) return;
    int n0 = blockIdx.x * BN;

    extern __shared__ char smem[];
    uint32_t sb = smem_u32(smem);
    int* s_src = (int*)(smem + SM_IDX);
    int* s_tgt = (int*)(smem + SM_IDX + 512);

    int tid = threadIdx.x, lane = tid & 31, w = tid >> 5;
    int wm = w >> 2, wn = w & 3;
    int g = lane >> 2, tg = lane & 3;

    if (tid < BM) {
        int slot = m0 + tid;
        if (slot < cnt) {
            int e = g_bucket[t][slot];
            s_src[tid] = eidx[e];
            s_tgt[tid] = eidx[NE + e];
        } else {
            s_src[tid] = 0;
            s_tgt[tid] = -1;
        }
    }
    __syncthreads();

    const float* Wt = g_wmtf + (size_t)t * DIM * DIM;

    // fill: 128 rows x 8 chunks = 1024 chunks per tile; 256 thr x p<4 = 1024
    auto fill = [&](int stg, int kk) {
        uint32_t ab = sb + SM_TILES + stg * STG_BYTES;
        uint32_t bbs = ab + A_STG_BYTES;
#pragma unroll
        for (int p = 0; p < 4; ++p) {
            int f = p * THREADS + tid;
            int row = f >> 3, q = f & 7;
            int qs = q ^ ((row & 1) << 2);
            cpa16(ab + row * (LDA * 4) + qs * 16,
                  g_xtf + (size_t)s_src[row] * DIM + kk + q * 4);
        }
#pragma unroll
        for (int p = 0; p < 4; ++p) {
            int f = p * THREADS + tid;
            int row = f >> 3, q = f & 7;
            int qs = q ^ ((row & 1) << 2);
            cpa16(bbs + row * (LDA * 4) + qs * 16,
                  Wt + (size_t)(n0 + row) * DIM + kk + q * 4);
        }
    };

    float c[4][4][4];
#pragma unroll
    for (int i = 0; i < 4; i++)
#pragma unroll
        for (int j = 0; j < 4; j++)
#pragma unroll
            for (int r = 0; r < 4; r++) c[i][j][r] = 0.f;

    const int KT = DIM / BK;   // 24
    fill(0, 0); cpa_commit();
    fill(1, BK); cpa_commit();

    for (int kt = 0; kt < KT; ++kt) {
        if (kt == KT - 1) cpa_wait0(); else cpa_wait1();
        __syncthreads();   // single barrier per slice (3-stage rotation is safe)
        const unsigned* As = (const unsigned*)(smem + SM_TILES + (kt % 3) * STG_BYTES);
        const unsigned* Bs = As + BM * LDA;
        compute_stage(As, Bs, c, wm, wn, g, tg);
        if (kt + 2 < KT) fill((kt + 2) % 3, (kt + 2) * BK);
        cpa_commit();      // unconditional: keeps wait_group accounting exact
    }

    // epilogue: + bias, vector-atomic scatter-add to target nodes
#pragma unroll
    for (int im = 0; im < 4; ++im) {
#pragma unroll
        for (int r2 = 0; r2 < 2; ++r2) {
            int rloc = wm * 64 + im * 16 + g + r2 * 8;
            int tgt = s_tgt[rloc];
            if (tgt < 0) continue;
            float* dst = g_agg + (size_t)tgt * DIM;
#pragma unroll
            for (int in_ = 0; in_ < 4; ++in_) {
                int col = n0 + wn * 32 + in_ * 8 + tg * 2;
                red2(dst + col,
                     c[im][in_][r2 * 2 + 0] + bm[t * DIM + col],
                     c[im][in_][r2 * 2 + 1] + bm[t * DIM + col + 1]);
            }
        }
    }
}

// ---------------------------------------------------------------------------
// K3: update GEMM  out = relu([X | agg] @ W_upd^T + b_upd)  (residual in k_ln)
//     grid (DIM/BN, ceil(NN/BM)), 256 threads, 2 CTA/SM
// ---------------------------------------------------------------------------
__global__ __launch_bounds__(THREADS, 2) void k_upd(const float* __restrict__ bu,
                                                    float* __restrict__ out) {
    int m0 = blockIdx.y * BM;
    int n0 = blockIdx.x * BN;

    extern __shared__ char smem[];
    uint32_t sb = smem_u32(smem);

    int tid = threadIdx.x, lane = tid & 31, w = tid >> 5;
    int wm = w >> 2, wn = w & 3;
    int g = lane >> 2, tg = lane & 3;

    auto fill = [&](int stg, int kk) {
        uint32_t ab = sb + SM_TILES + stg * STG_BYTES;
        uint32_t bbs = ab + A_STG_BYTES;
        const float* abase = (kk < DIM) ? g_xtf + kk : g_agg + (kk - DIM);
#pragma unroll
        for (int p = 0; p < 4; ++p) {
            int f = p * THREADS + tid;
            int row = f >> 3, q = f & 7;
            int qs = q ^ ((row & 1) << 2);
            int node = m0 + row; if (node >= NN) node = NN - 1;
            cpa16(ab + row * (LDA * 4) + qs * 16, abase + (size_t)node * DIM + q * 4);
        }
#pragma unroll
        for (int p = 0; p < 4; ++p) {
            int f = p * THREADS + tid;
            int row = f >> 3, q = f & 7;
            int qs = q ^ ((row & 1) << 2);
            cpa16(bbs + row * (LDA * 4) + qs * 16,
                  g_wutf + (size_t)(n0 + row) * DIM2 + kk + q * 4);
        }
    };

    float c[4][4][4];
#pragma unroll
    for (int i = 0; i < 4; i++)
#pragma unroll
        for (int j = 0; j < 4; j++)
#pragma unroll
            for (int r = 0; r < 4; r++) c[i][j][r] = 0.f;

    const int KT = DIM2 / BK;  // 48
    fill(0, 0); cpa_commit();
    fill(1, BK); cpa_commit();

    for (int kt = 0; kt < KT; ++kt) {
        if (kt == KT - 1) cpa_wait0(); else cpa_wait1();
        __syncthreads();
        const unsigned* As = (const unsigned*)(smem + SM_TILES + (kt % 3) * STG_BYTES);
        const unsigned* Bs = As + BM * LDA;
        compute_stage(As, Bs, c, wm, wn, g, tg);
        if (kt + 2 < KT) fill((kt + 2) % 3, (kt + 2) * BK);
        cpa_commit();
    }

    // epilogue: bias + relu, float2 stores
#pragma unroll
    for (int im = 0; im < 4; ++im) {
#pragma unroll
        for (int r2 = 0; r2 < 2; ++r2) {
            int rloc = wm * 64 + im * 16 + g + r2 * 8;
            int node = m0 + rloc;
            if (node >= NN) continue;
#pragma unroll
            for (int in_ = 0; in_ < 4; ++in_) {
                int col = n0 + wn * 32 + in_ * 8 + tg * 2;
                float2 o;
                o.x = fmaxf(c[im][in_][r2 * 2 + 0] + bu[col],     0.f);
                o.y = fmaxf(c[im][in_][r2 * 2 + 1] + bu[col + 1], 0.f);
                *reinterpret_cast<float2*>(out + (size_t)node * DIM + col) = o;
            }
        }
    }
}

// ---------------------------------------------------------------------------
// K4: out = LayerNorm(X + out)
// ---------------------------------------------------------------------------
__global__ __launch_bounds__(256) void k_ln(float* __restrict__ out,
                                            const float* __restrict__ X,
                                            const float* __restrict__ gamma,
                                            const float* __restrict__ beta) {
    __shared__ float red[34];
    int n = blockIdx.x;
    float* row = out + (size_t)n * DIM;
    const float* xr = X + (size_t)n * DIM;
    int tid = threadIdx.x;

    float v0 = row[tid]       + xr[tid];
    float v1 = row[tid + 256] + xr[tid + 256];
    float v2 = row[tid + 512] + xr[tid + 512];
    float s = v0 + v1 + v2;
    float s2 = v0 * v0 + v1 * v1 + v2 * v2;
#pragma unroll
    for (int o = 16; o > 0; o >>= 1) {
        s  += __shfl_xor_sync(0xffffffffu, s, o);
        s2 += __shfl_xor_sync(0xffffffffu, s2, o);
    }
    int w = tid >> 5, l = tid & 31;
    if (l == 0) { red[w] = s; red[8 + w] = s2; }
    __syncthreads();
    if (w == 0) {
        float a = (l < 8) ? red[l] : 0.f;
        float b = (l < 8) ? red[8 + l] : 0.f;
#pragma unroll
        for (int o = 4; o > 0; o >>= 1) {
            a += __shfl_xor_sync(0xffffffffu, a, o);
            b += __shfl_xor_sync(0xffffffffu, b, o);
        }
        if (l == 0) { red[32] = a; red[33] = b; }
    }
    __syncthreads();
    float mu = red[32] * (1.0f / DIM);
    float var = red[33] * (1.0f / DIM) - mu * mu;
    float inv = rsqrtf(var + LN_EPS);
    row[tid]       = (v0 - mu) * inv * gamma[tid]       + beta[tid];
    row[tid + 256] = (v1 - mu) * inv * gamma[tid + 256] + beta[tid + 256];
    row[tid + 512] = (v2 - mu) * inv * gamma[tid + 512] + beta[tid + 512];
}

// ---------------------------------------------------------------------------
// kernel_launch
// ---------------------------------------------------------------------------
extern "C" void kernel_launch(void* const* d_in, const int* in_sizes, int n_in,
                              void* d_out, int out_size) {
    const float* X   = (const float*)d_in[0];
    const float* Wm  = (const float*)d_in[1];
    const float* bm  = (const float*)d_in[2];
    const float* Wu  = (const float*)d_in[3];
    const float* bu  = (const float*)d_in[4];
    const float* gam = (const float*)d_in[5];
    const float* bet = (const float*)d_in[6];
    const int*   eidx= (const int*)d_in[7];
    const int*   etyp= (const int*)d_in[8];
    float* out = (float*)d_out;

    (void)in_sizes; (void)n_in; (void)out_size;

    cudaFuncSetAttribute(k_msg, cudaFuncAttributeMaxDynamicSharedMemorySize, SMEM_SZ);
    cudaFuncSetAttribute(k_upd, cudaFuncAttributeMaxDynamicSharedMemorySize, SMEM_SZ);

    float* xtf;  cudaGetSymbolAddress((void**)&xtf,  g_xtf);
    float* wmtf; cudaGetSymbolAddress((void**)&wmtf, g_wmtf);
    float* wutf; cudaGetSymbolAddress((void**)&wutf, g_wutf);
    float* agg;  cudaGetSymbolAddress((void**)&agg,  g_agg);

    k_init<<<4096, 256>>>();
    k_bucket<<<(NE + 255) / 256, 256>>>(etyp);

    // tf32-round + K-permute all inputs in one launch
    k_cvtp3<<<4096, 256>>>(X,  xtf,  (size_t)NN * DIM / 16,
                           Wm, wmtf, (size_t)NT * DIM * DIM / 16,
                           Wu, wutf, (size_t)DIM * DIM2 / 16);

    dim3 gm(DIM / BN, (NE + BM - 1) / BM, NT);
    k_msg<<<gm, THREADS, SMEM_SZ>>>(bm, eidx);

    // round + permute aggregated messages in place before the update GEMM
    k_cvtp<<<4096, 256>>>(agg, agg, (size_t)NN * DIM / 16);

    dim3 gu(DIM / BN, (NN + BM - 1) / BM);
    k_upd<<<gu, THREADS, SMEM_SZ>>>(bu, out);

    k_ln<<<NN, 256>>>(out, X, gam, bet);
}

// round 12
// speedup vs baseline: 1.0415x; 1.0415x over previous
#include <cuda_runtime.h>
#include <cstdint>
#include <cstddef>

// ---------------------------------------------------------------------------
// Problem constants
// ---------------------------------------------------------------------------
#define NN   100000
#define NE   100000
#define DIM  768
#define DIM2 1536
#define NT   5
#define LN_EPS 1e-5f

// Tiling (R10 config — best measured): CTA 128x128, 4 warps 2x2, warp tile
// 64x64, BK=32, 3 stages, LDA=32 + XOR swizzle, 1 barrier/slice, 2 CTA/SM.
#define BM 128
#define BN 128
#define BK 32
#define THREADS 128
#define LDA 32
#define A_STG_BYTES (BM * LDA * 4)          // 16384
#define B_STG_BYTES (BN * LDA * 4)          // 16384
#define STG_BYTES   (A_STG_BYTES + B_STG_BYTES)  // 32768
#define SM_IDX   0
#define SM_TILES 1024
#define SMEM_SZ  (SM_TILES + 3 * STG_BYTES)      // 99328

// ---------------------------------------------------------------------------
// Device scratch. tf32 copies stored K-PERMUTED: in each 16-float K-group,
// phys[4t+j] = logical[t+4j]. g_agg is accumulated DIRECTLY in permuted
// layout by k_msg's epilogue (contributions tf32-rounded before atomic).
// ---------------------------------------------------------------------------
__device__ float g_agg[(size_t)NN * DIM];
__device__ float g_xtf[(size_t)NN * DIM];
__device__ float g_wmtf[(size_t)NT * DIM * DIM];
__device__ float g_wutf[(size_t)DIM * DIM2];
__device__ int   g_bucket[NT][NE];
__device__ int   g_count[NT];

// ---------------------------------------------------------------------------
// Helpers
// ---------------------------------------------------------------------------
__device__ __forceinline__ uint32_t smem_u32(const void* p) {
    uint32_t a;
    asm("{ .reg .u64 t; cvta.to.shared.u64 t, %1; cvt.u32.u64 %0, t; }"
        : "=r"(a) : "l"(p));
    return a;
}

__device__ __forceinline__ void cpa16(uint32_t s, const void* g) {
    asm volatile("cp.async.cg.shared.global [%0], [%1], 16;"
                 :: "r"(s), "l"(g) : "memory");
}
__device__ __forceinline__ void cpa_commit() {
    asm volatile("cp.async.commit_group;" ::: "memory");
}
__device__ __forceinline__ void cpa_wait1() {
    asm volatile("cp.async.wait_group 1;" ::: "memory");
}
__device__ __forceinline__ void cpa_wait0() {
    asm volatile("cp.async.wait_group 0;" ::: "memory");
}

__device__ __forceinline__ float f2tf_f(float x) {
    unsigned r;
    asm("cvt.rna.tf32.f32 %0, %1;" : "=r"(r) : "f"(x));
    return __uint_as_float(r);
}

__device__ __forceinline__ void mma8(float& c0, float& c1, float& c2, float& c3,
                                     unsigned a0, unsigned a1, unsigned a2, unsigned a3,
                                     unsigned b0, unsigned b1) {
    asm volatile(
        "mma.sync.aligned.m16n8k8.row.col.f32.tf32.tf32.f32 "
        "{%0,%1,%2,%3}, {%4,%5,%6,%7}, {%8,%9}, {%0,%1,%2,%3};\n"
        : "+f"(c0), "+f"(c1), "+f"(c2), "+f"(c3)
        : "r"(a0), "r"(a1), "r"(a2), "r"(a3), "r"(b0), "r"(b1));
}

// one BK=32 slice on a 64x64 warp tile: 2 k-pairs, swizzled LDS.128 frags.
__device__ __forceinline__ void compute_stage(const unsigned* __restrict__ As,
                                              const unsigned* __restrict__ Bs,
                                              float c[4][8][4],
                                              int wm, int wn, int g, int tg) {
    int xorv = (g & 1) << 2;
#pragma unroll
    for (int kp = 0; kp < 2; ++kp) {
        int cf = ((kp * 4 + tg) ^ xorv) * 4;
        uint4 a[4][2], b[8];
#pragma unroll
        for (int im = 0; im < 4; ++im) {
            int mb = wm * 64 + im * 16;
            a[im][0] = *reinterpret_cast<const uint4*>(&As[(mb + g) * LDA + cf]);
            a[im][1] = *reinterpret_cast<const uint4*>(&As[(mb + g + 8) * LDA + cf]);
        }
#pragma unroll
        for (int in_ = 0; in_ < 8; ++in_) {
            int nb = wn * 64 + in_ * 8 + g;
            b[in_] = *reinterpret_cast<const uint4*>(&Bs[nb * LDA + cf]);
        }
#pragma unroll
        for (int im = 0; im < 4; ++im)
#pragma unroll
            for (int in_ = 0; in_ < 8; ++in_) {
                mma8(c[im][in_][0], c[im][in_][1], c[im][in_][2], c[im][in_][3],
                     a[im][0].x, a[im][1].x, a[im][0].y, a[im][1].y,
                     b[in_].x, b[in_].y);
                mma8(c[im][in_][0], c[im][in_][1], c[im][in_][2], c[im][in_][3],
                     a[im][0].z, a[im][1].z, a[im][0].w, a[im][1].w,
                     b[in_].z, b[in_].w);
            }
    }
}

// ---------------------------------------------------------------------------
// K0 / K1: init + bucket
// ---------------------------------------------------------------------------
__global__ void k_init() {
    size_t idx = (size_t)blockIdx.x * blockDim.x + threadIdx.x;
    if (idx < NT) g_count[idx] = 0;
    float4* p = reinterpret_cast<float4*>(g_agg);
    size_t n4 = (size_t)NN * DIM / 4;
    size_t stride = (size_t)gridDim.x * blockDim.x;
    for (size_t i = idx; i < n4; i += stride) p[i] = make_float4(0.f, 0.f, 0.f, 0.f);
}

__global__ void k_bucket(const int* __restrict__ etype) {
    int e = blockIdx.x * blockDim.x + threadIdx.x;
    if (e < NE) {
        int t = etype[e];
        int pos = atomicAdd(&g_count[t], 1);
        g_bucket[t][pos] = e;
    }
}

// tf32-round + K-permute one 16-float group
__device__ __forceinline__ void cvtp_group(const float* src, float* dst, size_t i) {
    const float4* s = reinterpret_cast<const float4*>(src) + i * 4;
    float4 v0 = s[0], v1 = s[1], v2 = s[2], v3 = s[3];
    float4* d = reinterpret_cast<float4*>(dst) + i * 4;
    float4 o;
    o.x = f2tf_f(v0.x); o.y = f2tf_f(v1.x); o.z = f2tf_f(v2.x); o.w = f2tf_f(v3.x);
    d[0] = o;
    o.x = f2tf_f(v0.y); o.y = f2tf_f(v1.y); o.z = f2tf_f(v2.y); o.w = f2tf_f(v3.y);
    d[1] = o;
    o.x = f2tf_f(v0.z); o.y = f2tf_f(v1.z); o.z = f2tf_f(v2.z); o.w = f2tf_f(v3.z);
    d[2] = o;
    o.x = f2tf_f(v0.w); o.y = f2tf_f(v1.w); o.z = f2tf_f(v2.w); o.w = f2tf_f(v3.w);
    d[3] = o;
}

__global__ void k_cvtp3(const float* s0, float* d0, size_t n0,
                        const float* s1, float* d1, size_t n1,
                        const float* s2, float* d2, size_t n2) {
    size_t idx = (size_t)blockIdx.x * blockDim.x + threadIdx.x;
    size_t stride = (size_t)gridDim.x * blockDim.x;
    size_t total = n0 + n1 + n2;
    for (size_t i = idx; i < total; i += stride) {
        if (i < n0) cvtp_group(s0, d0, i);
        else if (i < n0 + n1) cvtp_group(s1, d1, i - n0);
        else cvtp_group(s2, d2, i - n0 - n1);
    }
}

// ---------------------------------------------------------------------------
// K2: per-type gather-GEMM; epilogue rounds contributions to tf32 and
//     scatter-adds directly into PERMUTED g_agg (no separate agg pass).
//     grid (DIM/BN, ceil(NE/BM), NT), 128 threads, 2 CTA/SM
// ---------------------------------------------------------------------------
__global__ __launch_bounds__(THREADS, 2) void k_msg(const float* __restrict__ bm,
                                                    const int*   __restrict__ eidx) {
    int t = blockIdx.z;
    int cnt = g_count[t];
    int m0 = blockIdx.y * BM;
    if (m0 >= cnt) return;
    int n0 = blockIdx.x * BN;

    extern __shared__ char smem[];
    uint32_t sb = smem_u32(smem);
    int* s_src = (int*)(smem + SM_IDX);
    int* s_tgt = (int*)(smem + SM_IDX + 512);

    int tid = threadIdx.x, lane = tid & 31, w = tid >> 5;
    int wm = w >> 1, wn = w & 1;
    int g = lane >> 2, tg = lane & 3;

    {
        int slot = m0 + tid;
        if (slot < cnt) {
            int e = g_bucket[t][slot];
            s_src[tid] = eidx[e];
            s_tgt[tid] = eidx[NE + e];
        } else {
            s_src[tid] = 0;
            s_tgt[tid] = -1;
        }
    }
    __syncthreads();

    const float* Wt = g_wmtf + (size_t)t * DIM * DIM;

    // fill: 128 rows x 8 chunks = 1024 chunks; 128 threads x p<8
    auto fill = [&](int stg, int kk) {
        uint32_t ab = sb + SM_TILES + stg * STG_BYTES;
        uint32_t bbs = ab + A_STG_BYTES;
#pragma unroll
        for (int p = 0; p < 8; ++p) {
            int f = p * THREADS + tid;
            int row = f >> 3, q = f & 7;
            int qs = q ^ ((row & 1) << 2);
            cpa16(ab + row * (LDA * 4) + qs * 16,
                  g_xtf + (size_t)s_src[row] * DIM + kk + q * 4);
        }
#pragma unroll
        for (int p = 0; p < 8; ++p) {
            int f = p * THREADS + tid;
            int row = f >> 3, q = f & 7;
            int qs = q ^ ((row & 1) << 2);
            cpa16(bbs + row * (LDA * 4) + qs * 16,
                  Wt + (size_t)(n0 + row) * DIM + kk + q * 4);
        }
    };

    float c[4][8][4];
#pragma unroll
    for (int i = 0; i < 4; i++)
#pragma unroll
        for (int j = 0; j < 8; j++)
#pragma unroll
            for (int r = 0; r < 4; r++) c[i][j][r] = 0.f;

    const int KT = DIM / BK;   // 24
    fill(0, 0); cpa_commit();
    fill(1, BK); cpa_commit();

    for (int kt = 0; kt < KT; ++kt) {
        if (kt == KT - 1) cpa_wait0(); else cpa_wait1();
        __syncthreads();
        const unsigned* As = (const unsigned*)(smem + SM_TILES + (kt % 3) * STG_BYTES);
        const unsigned* Bs = As + BM * LDA;
        compute_stage(As, Bs, c, wm, wn, g, tg);
        if (kt + 2 < KT) fill((kt + 2) % 3, (kt + 2) * BK);
        cpa_commit();
    }

    // epilogue: + bias, round to tf32, scatter-add into PERMUTED g_agg.
    // logical col l -> within its 16-group: phys = 4*(l&3) + ((l>>2)&3)
#pragma unroll
    for (int im = 0; im < 4; ++im) {
#pragma unroll
        for (int r2 = 0; r2 < 2; ++r2) {
            int rloc = wm * 64 + im * 16 + g + r2 * 8;
            int tgt = s_tgt[rloc];
            if (tgt < 0) continue;
            float* dst = g_agg + (size_t)tgt * DIM;
#pragma unroll
            for (int in_ = 0; in_ < 8; ++in_) {
                int col = n0 + wn * 64 + in_ * 8 + tg * 2;   // even, col&1==0
                int base = col & ~15;
                int l16 = col & 15;                          // l16&3 == {0,2}
                int p0 = base + ((l16 & 3) << 2) + (l16 >> 2);
                // col+1: (l16+1)&3 = l16&3 + 1 (no wrap since l16 even), same >>2
                float v0 = f2tf_f(c[im][in_][r2 * 2 + 0] + bm[t * DIM + col]);
                float v1 = f2tf_f(c[im][in_][r2 * 2 + 1] + bm[t * DIM + col + 1]);
                atomicAdd(dst + p0, v0);
                atomicAdd(dst + p0 + 4, v1);
            }
        }
    }
}

// ---------------------------------------------------------------------------
// K3: update GEMM  out = relu([X | agg] @ W_upd^T + b_upd)  (residual in k_ln)
//     grid (DIM/BN, ceil(NN/BM)), 128 threads, 2 CTA/SM
// ---------------------------------------------------------------------------
__global__ __launch_bounds__(THREADS, 2) void k_upd(const float* __restrict__ bu,
                                                    float* __restrict__ out) {
    int m0 = blockIdx.y * BM;
    int n0 = blockIdx.x * BN;

    extern __shared__ char smem[];
    uint32_t sb = smem_u32(smem);

    int tid = threadIdx.x, lane = tid & 31, w = tid >> 5;
    int wm = w >> 1, wn = w & 1;
    int g = lane >> 2, tg = lane & 3;

    auto fill = [&](int stg, int kk) {
        uint32_t ab = sb + SM_TILES + stg * STG_BYTES;
        uint32_t bbs = ab + A_STG_BYTES;
        const float* abase = (kk < DIM) ? g_xtf + kk : g_agg + (kk - DIM);
#pragma unroll
        for (int p = 0; p < 8; ++p) {
            int f = p * THREADS + tid;
            int row = f >> 3, q = f & 7;
            int qs = q ^ ((row & 1) << 2);
            int node = m0 + row; if (node >= NN) node = NN - 1;
            cpa16(ab + row * (LDA * 4) + qs * 16, abase + (size_t)node * DIM + q * 4);
        }
#pragma unroll
        for (int p = 0; p < 8; ++p) {
            int f = p * THREADS + tid;
            int row = f >> 3, q = f & 7;
            int qs = q ^ ((row & 1) << 2);
            cpa16(bbs + row * (LDA * 4) + qs * 16,
                  g_wutf + (size_t)(n0 + row) * DIM2 + kk + q * 4);
        }
    };

    float c[4][8][4];
#pragma unroll
    for (int i = 0; i < 4; i++)
#pragma unroll
        for (int j = 0; j < 8; j++)
#pragma unroll
            for (int r = 0; r < 4; r++) c[i][j][r] = 0.f;

    const int KT = DIM2 / BK;  // 48
    fill(0, 0); cpa_commit();
    fill(1, BK); cpa_commit();

    for (int kt = 0; kt < KT; ++kt) {
        if (kt == KT - 1) cpa_wait0(); else cpa_wait1();
        __syncthreads();
        const unsigned* As = (const unsigned*)(smem + SM_TILES + (kt % 3) * STG_BYTES);
        const unsigned* Bs = As + BM * LDA;
        compute_stage(As, Bs, c, wm, wn, g, tg);
        if (kt + 2 < KT) fill((kt + 2) % 3, (kt + 2) * BK);
        cpa_commit();
    }

    // epilogue: bias + relu, float2 stores
#pragma unroll
    for (int im = 0; im < 4; ++im) {
#pragma unroll
        for (int r2 = 0; r2 < 2; ++r2) {
            int rloc = wm * 64 + im * 16 + g + r2 * 8;
            int node = m0 + rloc;
            if (node >= NN) continue;
#pragma unroll
            for (int in_ = 0; in_ < 8; ++in_) {
                int col = n0 + wn * 64 + in_ * 8 + tg * 2;
                float2 o;
                o.x = fmaxf(c[im][in_][r2 * 2 + 0] + bu[col],     0.f);
                o.y = fmaxf(c[im][in_][r2 * 2 + 1] + bu[col + 1], 0.f);
                *reinterpret_cast<float2*>(out + (size_t)node * DIM + col) = o;
            }
        }
    }
}

// ---------------------------------------------------------------------------
// K4: out = LayerNorm(X + out)
// ---------------------------------------------------------------------------
__global__ __launch_bounds__(256) void k_ln(float* __restrict__ out,
                                            const float* __restrict__ X,
                                            const float* __restrict__ gamma,
                                            const float* __restrict__ beta) {
    __shared__ float red[34];
    int n = blockIdx.x;
    float* row = out + (size_t)n * DIM;
    const float* xr = X + (size_t)n * DIM;
    int tid = threadIdx.x;

    float v0 = row[tid]       + xr[tid];
    float v1 = row[tid + 256] + xr[tid + 256];
    float v2 = row[tid + 512] + xr[tid + 512];
    float s = v0 + v1 + v2;
    float s2 = v0 * v0 + v1 * v1 + v2 * v2;
#pragma unroll
    for (int o = 16; o > 0; o >>= 1) {
        s  += __shfl_xor_sync(0xffffffffu, s, o);
        s2 += __shfl_xor_sync(0xffffffffu, s2, o);
    }
    int w = tid >> 5, l = tid & 31;
    if (l == 0) { red[w] = s; red[8 + w] = s2; }
    __syncthreads();
    if (w == 0) {
        float a = (l < 8) ? red[l] : 0.f;
        float b = (l < 8) ? red[8 + l] : 0.f;
#pragma unroll
        for (int o = 4; o > 0; o >>= 1) {
            a += __shfl_xor_sync(0xffffffffu, a, o);
            b += __shfl_xor_sync(0xffffffffu, b, o);
        }
        if (l == 0) { red[32] = a; red[33] = b; }
    }
    __syncthreads();
    float mu = red[32] * (1.0f / DIM);
    float var = red[33] * (1.0f / DIM) - mu * mu;
    float inv = rsqrtf(var + LN_EPS);
    row[tid]       = (v0 - mu) * inv * gamma[tid]       + beta[tid];
    row[tid + 256] = (v1 - mu) * inv * gamma[tid + 256] + beta[tid + 256];
    row[tid + 512] = (v2 - mu) * inv * gamma[tid + 512] + beta[tid + 512];
}

// ---------------------------------------------------------------------------
// kernel_launch
// ---------------------------------------------------------------------------
extern "C" void kernel_launch(void* const* d_in, const int* in_sizes, int n_in,
                              void* d_out, int out_size) {
    const float* X   = (const float*)d_in[0];
    const float* Wm  = (const float*)d_in[1];
    const float* bm  = (const float*)d_in[2];
    const float* Wu  = (const float*)d_in[3];
    const float* bu  = (const float*)d_in[4];
    const float* gam = (const float*)d_in[5];
    const float* bet = (const float*)d_in[6];
    const int*   eidx= (const int*)d_in[7];
    const int*   etyp= (const int*)d_in[8];
    float* out = (float*)d_out;

    (void)in_sizes; (void)n_in; (void)out_size;

    cudaFuncSetAttribute(k_msg, cudaFuncAttributeMaxDynamicSharedMemorySize, SMEM_SZ);
    cudaFuncSetAttribute(k_upd, cudaFuncAttributeMaxDynamicSharedMemorySize, SMEM_SZ);

    float* xtf;  cudaGetSymbolAddress((void**)&xtf,  g_xtf);
    float* wmtf; cudaGetSymbolAddress((void**)&wmtf, g_wmtf);
    float* wutf; cudaGetSymbolAddress((void**)&wutf, g_wutf);

    k_init<<<4096, 256>>>();
    k_bucket<<<(NE + 255) / 256, 256>>>(etyp);

    // tf32-round + K-permute all inputs in one launch
    k_cvtp3<<<4096, 256>>>(X,  xtf,  (size_t)NN * DIM / 16,
                           Wm, wmtf, (size_t)NT * DIM * DIM / 16,
                           Wu, wutf, (size_t)DIM * DIM2 / 16);

    dim3 gm(DIM / BN, (NE + BM - 1) / BM, NT);
    k_msg<<<gm, THREADS, SMEM_SZ>>>(bm, eidx);

    // (agg round+permute pass eliminated: k_msg scatters permuted tf32)

    dim3 gu(DIM / BN, (NN + BM - 1) / BM);
    k_upd<<<gu, THREADS, SMEM_SZ>>>(bu, out);

    k_ln<<<NN, 256>>>(out, X, gam, bet);
}

// round 13
// speedup vs baseline: 1.6414x; 1.5760x over previous
#include <cuda_runtime.h>
#include <cuda_fp16.h>
#include <cstdint>
#include <cstddef>

// ---------------------------------------------------------------------------
// Problem constants
// ---------------------------------------------------------------------------
#define NN   100000
#define NE   100000
#define DIM  768
#define DIM2 1536
#define NT   5
#define LN_EPS 1e-5f

// fp16 GEMM: CTA 128x128, 4 warps 2x2, warp tile 64x64, BK=64 halves,
// 3 stages x 32KB, XOR-swizzled 16B chunks, 1 barrier/slice, 2 CTA/SM.
// mma.m16n8k16.f16 with f32 accumulate (same 10-bit mantissa as tf32 -> same
// error profile, 2x throughput).
#define BM 128
#define BN 128
#define BK 64                   // halves per stage (128 B per row)
#define THREADS 128
#define ROWU 32                 // unsigned per smem row (128 B)
#define A_STG_BYTES (BM * 128)  // 16384
#define B_STG_BYTES (BN * 128)  // 16384
#define STG_BYTES   (A_STG_BYTES + B_STG_BYTES)  // 32768
#define SM_IDX   0
#define SM_TILES 1024
#define SMEM_SZ  (SM_TILES + 3 * STG_BYTES)      // 99328

// ---------------------------------------------------------------------------
// Device scratch (uint4 arrays for 16B alignment; viewed as __half).
// All fp16 data is K-PERMUTED within each 32-half group:
//   phys(l) = 8*((l>>1)&3) + 2*((l>>3)&3) + (l&1)
// so thread tg's 8 halves for two k16 MMA steps are one contiguous 16B chunk.
// ---------------------------------------------------------------------------
__device__ uint4 g_agg_v [(size_t)NN * DIM / 8];
__device__ uint4 g_xtf_v [(size_t)NN * DIM / 8];
__device__ uint4 g_wmtf_v[(size_t)NT * DIM * DIM / 8];
__device__ uint4 g_wutf_v[(size_t)DIM * DIM2 / 8];
__device__ int   g_bucket[NT][NE];
__device__ int   g_count[NT];

// ---------------------------------------------------------------------------
// Helpers
// ---------------------------------------------------------------------------
__device__ __forceinline__ uint32_t smem_u32(const void* p) {
    uint32_t a;
    asm("{ .reg .u64 t; cvta.to.shared.u64 t, %1; cvt.u32.u64 %0, t; }"
        : "=r"(a) : "l"(p));
    return a;
}

__device__ __forceinline__ void cpa16(uint32_t s, const void* g) {
    asm volatile("cp.async.cg.shared.global [%0], [%1], 16;"
                 :: "r"(s), "l"(g) : "memory");
}
__device__ __forceinline__ void cpa_commit() {
    asm volatile("cp.async.commit_group;" ::: "memory");
}
__device__ __forceinline__ void cpa_wait1() {
    asm volatile("cp.async.wait_group 1;" ::: "memory");
}
__device__ __forceinline__ void cpa_wait0() {
    asm volatile("cp.async.wait_group 0;" ::: "memory");
}

__device__ __forceinline__ void mma16(float& c0, float& c1, float& c2, float& c3,
                                      unsigned a0, unsigned a1, unsigned a2, unsigned a3,
                                      unsigned b0, unsigned b1) {
    asm volatile(
        "mma.sync.aligned.m16n8k16.row.col.f32.f16.f16.f32 "
        "{%0,%1,%2,%3}, {%4,%5,%6,%7}, {%8,%9}, {%0,%1,%2,%3};\n"
        : "+f"(c0), "+f"(c1), "+f"(c2), "+f"(c3)
        : "r"(a0), "r"(a1), "r"(a2), "r"(a3), "r"(b0), "r"(b1));
}

// one BK=64 slice on a 64x64 warp tile: 2 kp-groups x 2 k16-steps each.
// Per kp: one LDS.128 per row gives BOTH k16 steps' fragments.
__device__ __forceinline__ void compute_stage(const unsigned* __restrict__ As,
                                              const unsigned* __restrict__ Bs,
                                              float c[4][8][4],
                                              int wm, int wn, int g, int tg) {
    int xorv = (g & 1) << 2;
#pragma unroll
    for (int kp = 0; kp < 2; ++kp) {
        int cu = ((4 * kp + tg) ^ xorv) * 4;   // unsigned offset within row
        uint4 a[4][2], b[8];
#pragma unroll
        for (int im = 0; im < 4; ++im) {
            int mb = wm * 64 + im * 16;
            a[im][0] = *reinterpret_cast<const uint4*>(&As[(mb + g) * ROWU + cu]);
            a[im][1] = *reinterpret_cast<const uint4*>(&As[(mb + g + 8) * ROWU + cu]);
        }
#pragma unroll
        for (int in_ = 0; in_ < 8; ++in_) {
            int nb = wn * 64 + in_ * 8 + g;
            b[in_] = *reinterpret_cast<const uint4*>(&Bs[nb * ROWU + cu]);
        }
#pragma unroll
        for (int im = 0; im < 4; ++im)
#pragma unroll
            for (int in_ = 0; in_ < 8; ++in_) {
                mma16(c[im][in_][0], c[im][in_][1], c[im][in_][2], c[im][in_][3],
                      a[im][0].x, a[im][1].x, a[im][0].y, a[im][1].y,
                      b[in_].x, b[in_].y);
                mma16(c[im][in_][0], c[im][in_][1], c[im][in_][2], c[im][in_][3],
                      a[im][0].z, a[im][1].z, a[im][0].w, a[im][1].w,
                      b[in_].z, b[in_].w);
            }
    }
}

// ---------------------------------------------------------------------------
// K0 / K1: init + bucket
// ---------------------------------------------------------------------------
__global__ void k_init() {
    size_t idx = (size_t)blockIdx.x * blockDim.x + threadIdx.x;
    if (idx < NT) g_count[idx] = 0;
    size_t n = (size_t)NN * DIM / 8;
    size_t stride = (size_t)gridDim.x * blockDim.x;
    uint4 z = make_uint4(0, 0, 0, 0);
    for (size_t i = idx; i < n; i += stride) g_agg_v[i] = z;
}

__global__ void k_bucket(const int* __restrict__ etype) {
    int e = blockIdx.x * blockDim.x + threadIdx.x;
    if (e < NE) {
        int t = etype[e];
        int pos = atomicAdd(&g_count[t], 1);
        g_bucket[t][pos] = e;
    }
}

// f32 -> fp16(rn) + K-permute one 32-float group
__device__ __forceinline__ void cvtph_group(const float* src, __half* dst, size_t i) {
    const float4* s = reinterpret_cast<const float4*>(src) + i * 8;
    float in[32];
#pragma unroll
    for (int j = 0; j < 8; ++j) {
        float4 v = s[j];
        in[j * 4] = v.x; in[j * 4 + 1] = v.y; in[j * 4 + 2] = v.z; in[j * 4 + 3] = v.w;
    }
    __half2 out[16];
#pragma unroll
    for (int ph = 0; ph < 16; ++ph) {
        int p = ph * 2;                               // even phys index
        int l = ((p >> 3) << 1) + (((p >> 1) & 3) << 3);  // logical index
        out[ph] = __floats2half2_rn(in[l], in[l + 1]);
    }
    uint4* d = reinterpret_cast<uint4*>(dst + i * 32);
    const uint4* o = reinterpret_cast<const uint4*>(out);
    d[0] = o[0]; d[1] = o[1]; d[2] = o[2]; d[3] = o[3];
}

__global__ void k_cvtp3(const float* s0, __half* d0, size_t n0,
                        const float* s1, __half* d1, size_t n1,
                        const float* s2, __half* d2, size_t n2) {
    size_t idx = (size_t)blockIdx.x * blockDim.x + threadIdx.x;
    size_t stride = (size_t)gridDim.x * blockDim.x;
    size_t total = n0 + n1 + n2;
    for (size_t i = idx; i < total; i += stride) {
        if (i < n0) cvtph_group(s0, d0, i);
        else if (i < n0 + n1) cvtph_group(s1, d1, i - n0);
        else cvtph_group(s2, d2, i - n0 - n1);
    }
}

// ---------------------------------------------------------------------------
// K2: per-type gather-GEMM (fp16); epilogue rounds to fp16 and half2-atomic
//     scatter-adds into PERMUTED g_agg. grid (6, 782, 5), 128 thr, 2 CTA/SM
// ---------------------------------------------------------------------------
__global__ __launch_bounds__(THREADS, 2) void k_msg(const float* __restrict__ bm,
                                                    const int*   __restrict__ eidx) {
    int t = blockIdx.z;
    int cnt = g_count[t];
    int m0 = blockIdx.y * BM;
    if (m0 >= cnt) return;
    int n0 = blockIdx.x * BN;

    extern __shared__ char smem[];
    uint32_t sb = smem_u32(smem);
    int* s_src = (int*)(smem + SM_IDX);
    int* s_tgt = (int*)(smem + SM_IDX + 512);

    int tid = threadIdx.x, lane = tid & 31, w = tid >> 5;
    int wm = w >> 1, wn = w & 1;
    int g = lane >> 2, tg = lane & 3;

    {
        int slot = m0 + tid;
        if (slot < cnt) {
            int e = g_bucket[t][slot];
            s_src[tid] = eidx[e];
            s_tgt[tid] = eidx[NE + e];
        } else {
            s_src[tid] = 0;
            s_tgt[tid] = -1;
        }
    }
    __syncthreads();

    const __half* Xh = (const __half*)g_xtf_v;
    const __half* Wt = (const __half*)g_wmtf_v + (size_t)t * DIM * DIM;

    // fill: 128 rows x 8 chunks(16B) = 1024 chunks; 128 threads x p<8
    auto fill = [&](int stg, int kk) {
        uint32_t ab = sb + SM_TILES + stg * STG_BYTES;
        uint32_t bbs = ab + A_STG_BYTES;
#pragma unroll
        for (int p = 0; p < 8; ++p) {
            int f = p * THREADS + tid;
            int row = f >> 3, q = f & 7;
            int qs = q ^ ((row & 1) << 2);
            cpa16(ab + row * 128 + qs * 16,
                  Xh + (size_t)s_src[row] * DIM + kk + q * 8);
        }
#pragma unroll
        for (int p = 0; p < 8; ++p) {
            int f = p * THREADS + tid;
            int row = f >> 3, q = f & 7;
            int qs = q ^ ((row & 1) << 2);
            cpa16(bbs + row * 128 + qs * 16,
                  Wt + (size_t)(n0 + row) * DIM + kk + q * 8);
        }
    };

    float c[4][8][4];
#pragma unroll
    for (int i = 0; i < 4; i++)
#pragma unroll
        for (int j = 0; j < 8; j++)
#pragma unroll
            for (int r = 0; r < 4; r++) c[i][j][r] = 0.f;

    const int KT = DIM / BK;   // 12
    fill(0, 0); cpa_commit();
    fill(1, BK); cpa_commit();

    for (int kt = 0; kt < KT; ++kt) {
        if (kt == KT - 1) cpa_wait0(); else cpa_wait1();
        __syncthreads();
        const unsigned* As = (const unsigned*)(smem + SM_TILES + (kt % 3) * STG_BYTES);
        const unsigned* Bs = As + BM * ROWU;
        compute_stage(As, Bs, c, wm, wn, g, tg);
        if (kt + 2 < KT) fill((kt + 2) % 3, (kt + 2) * BK);
        cpa_commit();
    }

    // epilogue: + bias, fp16-round, half2 atomic into PERMUTED g_agg.
    // logical col l (even): phys within 32-group = 8*((l>>1)&3) + 2*((l>>3)&3);
    // col+1 lands at phys+1 -> one aligned half2.
    __half* aggh = (__half*)g_agg_v;
#pragma unroll
    for (int im = 0; im < 4; ++im) {
#pragma unroll
        for (int r2 = 0; r2 < 2; ++r2) {
            int rloc = wm * 64 + im * 16 + g + r2 * 8;
            int tgt = s_tgt[rloc];
            if (tgt < 0) continue;
            __half* dst = aggh + (size_t)tgt * DIM;
#pragma unroll
            for (int in_ = 0; in_ < 8; ++in_) {
                int col = n0 + wn * 64 + in_ * 8 + tg * 2;
                int base = col & ~31;
                int l32 = col & 31;
                int p = (((l32 >> 1) & 3) << 3) + (((l32 >> 3) & 3) << 1);
                float v0 = c[im][in_][r2 * 2 + 0] + bm[t * DIM + col];
                float v1 = c[im][in_][r2 * 2 + 1] + bm[t * DIM + col + 1];
                atomicAdd(reinterpret_cast<__half2*>(dst + base + p),
                          __floats2half2_rn(v0, v1));
            }
        }
    }
}

// ---------------------------------------------------------------------------
// K3: update GEMM (fp16)  out = relu([X | agg] @ W_upd^T + b_upd)
//     grid (6, 782), 128 threads, 2 CTA/SM
// ---------------------------------------------------------------------------
__global__ __launch_bounds__(THREADS, 2) void k_upd(const float* __restrict__ bu,
                                                    float* __restrict__ out) {
    int m0 = blockIdx.y * BM;
    int n0 = blockIdx.x * BN;

    extern __shared__ char smem[];
    uint32_t sb = smem_u32(smem);

    int tid = threadIdx.x, lane = tid & 31, w = tid >> 5;
    int wm = w >> 1, wn = w & 1;
    int g = lane >> 2, tg = lane & 3;

    const __half* Xh = (const __half*)g_xtf_v;
    const __half* Ah = (const __half*)g_agg_v;
    const __half* Wu = (const __half*)g_wutf_v;

    auto fill = [&](int stg, int kk) {
        uint32_t ab = sb + SM_TILES + stg * STG_BYTES;
        uint32_t bbs = ab + A_STG_BYTES;
        const __half* abase = (kk < DIM) ? Xh + kk : Ah + (kk - DIM);
#pragma unroll
        for (int p = 0; p < 8; ++p) {
            int f = p * THREADS + tid;
            int row = f >> 3, q = f & 7;
            int qs = q ^ ((row & 1) << 2);
            int node = m0 + row; if (node >= NN) node = NN - 1;
            cpa16(ab + row * 128 + qs * 16, abase + (size_t)node * DIM + q * 8);
        }
#pragma unroll
        for (int p = 0; p < 8; ++p) {
            int f = p * THREADS + tid;
            int row = f >> 3, q = f & 7;
            int qs = q ^ ((row & 1) << 2);
            cpa16(bbs + row * 128 + qs * 16,
                  Wu + (size_t)(n0 + row) * DIM2 + kk + q * 8);
        }
    };

    float c[4][8][4];
#pragma unroll
    for (int i = 0; i < 4; i++)
#pragma unroll
        for (int j = 0; j < 8; j++)
#pragma unroll
            for (int r = 0; r < 4; r++) c[i][j][r] = 0.f;

    const int KT = DIM2 / BK;  // 24
    fill(0, 0); cpa_commit();
    fill(1, BK); cpa_commit();

    for (int kt = 0; kt < KT; ++kt) {
        if (kt == KT - 1) cpa_wait0(); else cpa_wait1();
        __syncthreads();
        const unsigned* As = (const unsigned*)(smem + SM_TILES + (kt % 3) * STG_BYTES);
        const unsigned* Bs = As + BM * ROWU;
        compute_stage(As, Bs, c, wm, wn, g, tg);
        if (kt + 2 < KT) fill((kt + 2) % 3, (kt + 2) * BK);
        cpa_commit();
    }

    // epilogue: bias + relu, float2 stores
#pragma unroll
    for (int im = 0; im < 4; ++im) {
#pragma unroll
        for (int r2 = 0; r2 < 2; ++r2) {
            int rloc = wm * 64 + im * 16 + g + r2 * 8;
            int node = m0 + rloc;
            if (node >= NN) continue;
#pragma unroll
            for (int in_ = 0; in_ < 8; ++in_) {
                int col = n0 + wn * 64 + in_ * 8 + tg * 2;
                float2 o;
                o.x = fmaxf(c[im][in_][r2 * 2 + 0] + bu[col],     0.f);
                o.y = fmaxf(c[im][in_][r2 * 2 + 1] + bu[col + 1], 0.f);
                *reinterpret_cast<float2*>(out + (size_t)node * DIM + col) = o;
            }
        }
    }
}

// ---------------------------------------------------------------------------
// K4: out = LayerNorm(X + out)   (full-precision X residual)
// ---------------------------------------------------------------------------
__global__ __launch_bounds__(256) void k_ln(float* __restrict__ out,
                                            const float* __restrict__ X,
                                            const float* __restrict__ gamma,
                                            const float* __restrict__ beta) {
    __shared__ float red[34];
    int n = blockIdx.x;
    float* row = out + (size_t)n * DIM;
    const float* xr = X + (size_t)n * DIM;
    int tid = threadIdx.x;

    float v0 = row[tid]       + xr[tid];
    float v1 = row[tid + 256] + xr[tid + 256];
    float v2 = row[tid + 512] + xr[tid + 512];
    float s = v0 + v1 + v2;
    float s2 = v0 * v0 + v1 * v1 + v2 * v2;
#pragma unroll
    for (int o = 16; o > 0; o >>= 1) {
        s  += __shfl_xor_sync(0xffffffffu, s, o);
        s2 += __shfl_xor_sync(0xffffffffu, s2, o);
    }
    int w = tid >> 5, l = tid & 31;
    if (l == 0) { red[w] = s; red[8 + w] = s2; }
    __syncthreads();
    if (w == 0) {
        float a = (l < 8) ? red[l] : 0.f;
        float b = (l < 8) ? red[8 + l] : 0.f;
#pragma unroll
        for (int o = 4; o > 0; o >>= 1) {
            a += __shfl_xor_sync(0xffffffffu, a, o);
            b += __shfl_xor_sync(0xffffffffu, b, o);
        }
        if (l == 0) { red[32] = a; red[33] = b; }
    }
    __syncthreads();
    float mu = red[32] * (1.0f / DIM);
    float var = red[33] * (1.0f / DIM) - mu * mu;
    float inv = rsqrtf(var + LN_EPS);
    row[tid]       = (v0 - mu) * inv * gamma[tid]       + beta[tid];
    row[tid + 256] = (v1 - mu) * inv * gamma[tid + 256] + beta[tid + 256];
    row[tid + 512] = (v2 - mu) * inv * gamma[tid + 512] + beta[tid + 512];
}

// ---------------------------------------------------------------------------
// kernel_launch
// ---------------------------------------------------------------------------
extern "C" void kernel_launch(void* const* d_in, const int* in_sizes, int n_in,
                              void* d_out, int out_size) {
    const float* X   = (const float*)d_in[0];
    const float* Wm  = (const float*)d_in[1];
    const float* bm  = (const float*)d_in[2];
    const float* Wu  = (const float*)d_in[3];
    const float* bu  = (const float*)d_in[4];
    const float* gam = (const float*)d_in[5];
    const float* bet = (const float*)d_in[6];
    const int*   eidx= (const int*)d_in[7];
    const int*   etyp= (const int*)d_in[8];
    float* out = (float*)d_out;

    (void)in_sizes; (void)n_in; (void)out_size;

    cudaFuncSetAttribute(k_msg, cudaFuncAttributeMaxDynamicSharedMemorySize, SMEM_SZ);
    cudaFuncSetAttribute(k_upd, cudaFuncAttributeMaxDynamicSharedMemorySize, SMEM_SZ);

    void* xtf;  cudaGetSymbolAddress(&xtf,  g_xtf_v);
    void* wmtf; cudaGetSymbolAddress(&wmtf, g_wmtf_v);
    void* wutf; cudaGetSymbolAddress(&wutf, g_wutf_v);

    k_init<<<4096, 256>>>();
    k_bucket<<<(NE + 255) / 256, 256>>>(etyp);

    // f32 -> fp16(rn) + K-permute all inputs in one launch
    k_cvtp3<<<4096, 256>>>(X,  (__half*)xtf,  (size_t)NN * DIM / 32,
                           Wm, (__half*)wmtf, (size_t)NT * DIM * DIM / 32,
                           Wu, (__half*)wutf, (size_t)DIM * DIM2 / 32);

    dim3 gm(DIM / BN, (NE + BM - 1) / BM, NT);
    k_msg<<<gm, THREADS, SMEM_SZ>>>(bm, eidx);

    dim3 gu(DIM / BN, (NN + BM - 1) / BM);
    k_upd<<<gu, THREADS, SMEM_SZ>>>(bu, out);

    k_ln<<<NN, 256>>>(out, X, gam, bet);
}

// round 14
// speedup vs baseline: 1.6910x; 1.0302x over previous
#include <cuda_runtime.h>
#include <cuda_fp16.h>
#include <cstdint>
#include <cstddef>

// ---------------------------------------------------------------------------
// Problem constants
// ---------------------------------------------------------------------------
#define NN   100000
#define NE   100000
#define DIM  768
#define DIM2 1536
#define NT   5
#define LN_EPS 1e-5f

// fp16 GEMM: CTA 128x128, 8 warps 2x4, warp tile 64x32, BK=64 halves,
// 3 stages x 32KB, XOR-swizzled 16B chunks, 1 barrier/slice, 2 CTA/SM
// -> 16 warps/SM (4/SMSP) to cover LDS/barrier latency.
#define BM 128
#define BN 128
#define BK 64                   // halves per stage (128 B per row)
#define THREADS 256
#define ROWU 32                 // unsigned per smem row (128 B)
#define A_STG_BYTES (BM * 128)  // 16384
#define B_STG_BYTES (BN * 128)  // 16384
#define STG_BYTES   (A_STG_BYTES + B_STG_BYTES)  // 32768
#define SM_IDX   0
#define SM_TILES 1024
#define SMEM_SZ  (SM_TILES + 3 * STG_BYTES)      // 99328

// ---------------------------------------------------------------------------
// Device scratch (uint4 arrays for 16B alignment; viewed as __half).
// fp16 data K-PERMUTED within each 32-half group:
//   phys(l) = 8*((l>>1)&3) + 2*((l>>3)&3) + (l&1)
// ---------------------------------------------------------------------------
__device__ uint4 g_agg_v [(size_t)NN * DIM / 8];
__device__ uint4 g_xtf_v [(size_t)NN * DIM / 8];
__device__ uint4 g_wmtf_v[(size_t)NT * DIM * DIM / 8];
__device__ uint4 g_wutf_v[(size_t)DIM * DIM2 / 8];
__device__ int   g_bucket[NT][NE];
__device__ int   g_count[NT];

// ---------------------------------------------------------------------------
// Helpers
// ---------------------------------------------------------------------------
__device__ __forceinline__ uint32_t smem_u32(const void* p) {
    uint32_t a;
    asm("{ .reg .u64 t; cvta.to.shared.u64 t, %1; cvt.u32.u64 %0, t; }"
        : "=r"(a) : "l"(p));
    return a;
}

__device__ __forceinline__ void cpa16(uint32_t s, const void* g) {
    asm volatile("cp.async.cg.shared.global [%0], [%1], 16;"
                 :: "r"(s), "l"(g) : "memory");
}
__device__ __forceinline__ void cpa_commit() {
    asm volatile("cp.async.commit_group;" ::: "memory");
}
__device__ __forceinline__ void cpa_wait1() {
    asm volatile("cp.async.wait_group 1;" ::: "memory");
}
__device__ __forceinline__ void cpa_wait0() {
    asm volatile("cp.async.wait_group 0;" ::: "memory");
}

__device__ __forceinline__ void mma16(float& c0, float& c1, float& c2, float& c3,
                                      unsigned a0, unsigned a1, unsigned a2, unsigned a3,
                                      unsigned b0, unsigned b1) {
    asm volatile(
        "mma.sync.aligned.m16n8k16.row.col.f32.f16.f16.f32 "
        "{%0,%1,%2,%3}, {%4,%5,%6,%7}, {%8,%9}, {%0,%1,%2,%3};\n"
        : "+f"(c0), "+f"(c1), "+f"(c2), "+f"(c3)
        : "r"(a0), "r"(a1), "r"(a2), "r"(a3), "r"(b0), "r"(b1));
}

// one BK=64 slice on a 64x32 warp tile: 2 kp-groups x 2 k16-steps each.
__device__ __forceinline__ void compute_stage(const unsigned* __restrict__ As,
                                              const unsigned* __restrict__ Bs,
                                              float c[4][4][4],
                                              int wm, int wn, int g, int tg) {
    int xorv = (g & 1) << 2;
#pragma unroll
    for (int kp = 0; kp < 2; ++kp) {
        int cu = ((4 * kp + tg) ^ xorv) * 4;   // unsigned offset within row
        uint4 a[4][2], b[4];
#pragma unroll
        for (int im = 0; im < 4; ++im) {
            int mb = wm * 64 + im * 16;
            a[im][0] = *reinterpret_cast<const uint4*>(&As[(mb + g) * ROWU + cu]);
            a[im][1] = *reinterpret_cast<const uint4*>(&As[(mb + g + 8) * ROWU + cu]);
        }
#pragma unroll
        for (int in_ = 0; in_ < 4; ++in_) {
            int nb = wn * 32 + in_ * 8 + g;
            b[in_] = *reinterpret_cast<const uint4*>(&Bs[nb * ROWU + cu]);
        }
#pragma unroll
        for (int im = 0; im < 4; ++im)
#pragma unroll
            for (int in_ = 0; in_ < 4; ++in_) {
                mma16(c[im][in_][0], c[im][in_][1], c[im][in_][2], c[im][in_][3],
                      a[im][0].x, a[im][1].x, a[im][0].y, a[im][1].y,
                      b[in_].x, b[in_].y);
                mma16(c[im][in_][0], c[im][in_][1], c[im][in_][2], c[im][in_][3],
                      a[im][0].z, a[im][1].z, a[im][0].w, a[im][1].w,
                      b[in_].z, b[in_].w);
            }
    }
}

// ---------------------------------------------------------------------------
// K0 / K1: init + bucket
// ---------------------------------------------------------------------------
__global__ void k_init() {
    size_t idx = (size_t)blockIdx.x * blockDim.x + threadIdx.x;
    if (idx < NT) g_count[idx] = 0;
    size_t n = (size_t)NN * DIM / 8;
    size_t stride = (size_t)gridDim.x * blockDim.x;
    uint4 z = make_uint4(0, 0, 0, 0);
    for (size_t i = idx; i < n; i += stride) g_agg_v[i] = z;
}

__global__ void k_bucket(const int* __restrict__ etype) {
    int e = blockIdx.x * blockDim.x + threadIdx.x;
    if (e < NE) {
        int t = etype[e];
        int pos = atomicAdd(&g_count[t], 1);
        g_bucket[t][pos] = e;
    }
}

// f32 -> fp16(rn) + K-permute one 32-float group
__device__ __forceinline__ void cvtph_group(const float* src, __half* dst, size_t i) {
    const float4* s = reinterpret_cast<const float4*>(src) + i * 8;
    float in[32];
#pragma unroll
    for (int j = 0; j < 8; ++j) {
        float4 v = s[j];
        in[j * 4] = v.x; in[j * 4 + 1] = v.y; in[j * 4 + 2] = v.z; in[j * 4 + 3] = v.w;
    }
    __half2 out[16];
#pragma unroll
    for (int ph = 0; ph < 16; ++ph) {
        int p = ph * 2;                               // even phys index
        int l = ((p >> 3) << 1) + (((p >> 1) & 3) << 3);  // logical index
        out[ph] = __floats2half2_rn(in[l], in[l + 1]);
    }
    uint4* d = reinterpret_cast<uint4*>(dst + i * 32);
    const uint4* o = reinterpret_cast<const uint4*>(out);
    d[0] = o[0]; d[1] = o[1]; d[2] = o[2]; d[3] = o[3];
}

__global__ void k_cvtp3(const float* s0, __half* d0, size_t n0,
                        const float* s1, __half* d1, size_t n1,
                        const float* s2, __half* d2, size_t n2) {
    size_t idx = (size_t)blockIdx.x * blockDim.x + threadIdx.x;
    size_t stride = (size_t)gridDim.x * blockDim.x;
    size_t total = n0 + n1 + n2;
    for (size_t i = idx; i < total; i += stride) {
        if (i < n0) cvtph_group(s0, d0, i);
        else if (i < n0 + n1) cvtph_group(s1, d1, i - n0);
        else cvtph_group(s2, d2, i - n0 - n1);
    }
}

// ---------------------------------------------------------------------------
// K2: per-type gather-GEMM (fp16); epilogue rounds to fp16 and half2-atomic
//     scatter-adds into PERMUTED g_agg. grid (6, 782, 5), 256 thr, 2 CTA/SM
// ---------------------------------------------------------------------------
__global__ __launch_bounds__(THREADS, 2) void k_msg(const float* __restrict__ bm,
                                                    const int*   __restrict__ eidx) {
    int t = blockIdx.z;
    int cnt = g_count[t];
    int m0 = blockIdx.y * BM;
    if (m0 >= cnt) return;
    int n0 = blockIdx.x * BN;

    extern __shared__ char smem[];
    uint32_t sb = smem_u32(smem);
    int* s_src = (int*)(smem + SM_IDX);
    int* s_tgt = (int*)(smem + SM_IDX + 512);

    int tid = threadIdx.x, lane = tid & 31, w = tid >> 5;
    int wm = w >> 2, wn = w & 3;
    int g = lane >> 2, tg = lane & 3;

    if (tid < BM) {
        int slot = m0 + tid;
        if (slot < cnt) {
            int e = g_bucket[t][slot];
            s_src[tid] = eidx[e];
            s_tgt[tid] = eidx[NE + e];
        } else {
            s_src[tid] = 0;
            s_tgt[tid] = -1;
        }
    }
    __syncthreads();

    const __half* Xh = (const __half*)g_xtf_v;
    const __half* Wt = (const __half*)g_wmtf_v + (size_t)t * DIM * DIM;

    // fill: 128 rows x 8 chunks(16B) = 1024 chunks; 256 threads x p<4
    auto fill = [&](int stg, int kk) {
        uint32_t ab = sb + SM_TILES + stg * STG_BYTES;
        uint32_t bbs = ab + A_STG_BYTES;
#pragma unroll
        for (int p = 0; p < 4; ++p) {
            int f = p * THREADS + tid;
            int row = f >> 3, q = f & 7;
            int qs = q ^ ((row & 1) << 2);
            cpa16(ab + row * 128 + qs * 16,
                  Xh + (size_t)s_src[row] * DIM + kk + q * 8);
        }
#pragma unroll
        for (int p = 0; p < 4; ++p) {
            int f = p * THREADS + tid;
            int row = f >> 3, q = f & 7;
            int qs = q ^ ((row & 1) << 2);
            cpa16(bbs + row * 128 + qs * 16,
                  Wt + (size_t)(n0 + row) * DIM + kk + q * 8);
        }
    };

    float c[4][4][4];
#pragma unroll
    for (int i = 0; i < 4; i++)
#pragma unroll
        for (int j = 0; j < 4; j++)
#pragma unroll
            for (int r = 0; r < 4; r++) c[i][j][r] = 0.f;

    const int KT = DIM / BK;   // 12
    fill(0, 0); cpa_commit();
    fill(1, BK); cpa_commit();

    for (int kt = 0; kt < KT; ++kt) {
        if (kt == KT - 1) cpa_wait0(); else cpa_wait1();
        __syncthreads();
        const unsigned* As = (const unsigned*)(smem + SM_TILES + (kt % 3) * STG_BYTES);
        const unsigned* Bs = As + BM * ROWU;
        compute_stage(As, Bs, c, wm, wn, g, tg);
        if (kt + 2 < KT) fill((kt + 2) % 3, (kt + 2) * BK);
        cpa_commit();
    }

    // epilogue: + bias, fp16-round, half2 atomic into PERMUTED g_agg.
    __half* aggh = (__half*)g_agg_v;
#pragma unroll
    for (int im = 0; im < 4; ++im) {
#pragma unroll
        for (int r2 = 0; r2 < 2; ++r2) {
            int rloc = wm * 64 + im * 16 + g + r2 * 8;
            int tgt = s_tgt[rloc];
            if (tgt < 0) continue;
            __half* dst = aggh + (size_t)tgt * DIM;
#pragma unroll
            for (int in_ = 0; in_ < 4; ++in_) {
                int col = n0 + wn * 32 + in_ * 8 + tg * 2;
                int base = col & ~31;
                int l32 = col & 31;
                int p = (((l32 >> 1) & 3) << 3) + (((l32 >> 3) & 3) << 1);
                float v0 = c[im][in_][r2 * 2 + 0] + bm[t * DIM + col];
                float v1 = c[im][in_][r2 * 2 + 1] + bm[t * DIM + col + 1];
                atomicAdd(reinterpret_cast<__half2*>(dst + base + p),
                          __floats2half2_rn(v0, v1));
            }
        }
    }
}

// ---------------------------------------------------------------------------
// K3: update GEMM (fp16)  out = relu([X | agg] @ W_upd^T + b_upd)
//     grid (6, 782), 256 threads, 2 CTA/SM
// ---------------------------------------------------------------------------
__global__ __launch_bounds__(THREADS, 2) void k_upd(const float* __restrict__ bu,
                                                    float* __restrict__ out) {
    int m0 = blockIdx.y * BM;
    int n0 = blockIdx.x * BN;

    extern __shared__ char smem[];
    uint32_t sb = smem_u32(smem);

    int tid = threadIdx.x, lane = tid & 31, w = tid >> 5;
    int wm = w >> 2, wn = w & 3;
    int g = lane >> 2, tg = lane & 3;

    const __half* Xh = (const __half*)g_xtf_v;
    const __half* Ah = (const __half*)g_agg_v;
    const __half* Wu = (const __half*)g_wutf_v;

    auto fill = [&](int stg, int kk) {
        uint32_t ab = sb + SM_TILES + stg * STG_BYTES;
        uint32_t bbs = ab + A_STG_BYTES;
        const __half* abase = (kk < DIM) ? Xh + kk : Ah + (kk - DIM);
#pragma unroll
        for (int p = 0; p < 4; ++p) {
            int f = p * THREADS + tid;
            int row = f >> 3, q = f & 7;
            int qs = q ^ ((row & 1) << 2);
            int node = m0 + row; if (node >= NN) node = NN - 1;
            cpa16(ab + row * 128 + qs * 16, abase + (size_t)node * DIM + q * 8);
        }
#pragma unroll
        for (int p = 0; p < 4; ++p) {
            int f = p * THREADS + tid;
            int row = f >> 3, q = f & 7;
            int qs = q ^ ((row & 1) << 2);
            cpa16(bbs + row * 128 + qs * 16,
                  Wu + (size_t)(n0 + row) * DIM2 + kk + q * 8);
        }
    };

    float c[4][4][4];
#pragma unroll
    for (int i = 0; i < 4; i++)
#pragma unroll
        for (int j = 0; j < 4; j++)
#pragma unroll
            for (int r = 0; r < 4; r++) c[i][j][r] = 0.f;

    const int KT = DIM2 / BK;  // 24
    fill(0, 0); cpa_commit();
    fill(1, BK); cpa_commit();

    for (int kt = 0; kt < KT; ++kt) {
        if (kt == KT - 1) cpa_wait0(); else cpa_wait1();
        __syncthreads();
        const unsigned* As = (const unsigned*)(smem + SM_TILES + (kt % 3) * STG_BYTES);
        const unsigned* Bs = As + BM * ROWU;
        compute_stage(As, Bs, c, wm, wn, g, tg);
        if (kt + 2 < KT) fill((kt + 2) % 3, (kt + 2) * BK);
        cpa_commit();
    }

    // epilogue: bias + relu, float2 stores
#pragma unroll
    for (int im = 0; im < 4; ++im) {
#pragma unroll
        for (int r2 = 0; r2 < 2; ++r2) {
            int rloc = wm * 64 + im * 16 + g + r2 * 8;
            int node = m0 + rloc;
            if (node >= NN) continue;
#pragma unroll
            for (int in_ = 0; in_ < 4; ++in_) {
                int col = n0 + wn * 32 + in_ * 8 + tg * 2;
                float2 o;
                o.x = fmaxf(c[im][in_][r2 * 2 + 0] + bu[col],     0.f);
                o.y = fmaxf(c[im][in_][r2 * 2 + 1] + bu[col + 1], 0.f);
                *reinterpret_cast<float2*>(out + (size_t)node * DIM + col) = o;
            }
        }
    }
}

// ---------------------------------------------------------------------------
// K4: out = LayerNorm(X + out)   (full-precision X residual)
// ---------------------------------------------------------------------------
__global__ __launch_bounds__(256) void k_ln(float* __restrict__ out,
                                            const float* __restrict__ X,
                                            const float* __restrict__ gamma,
                                            const float* __restrict__ beta) {
    __shared__ float red[34];
    int n = blockIdx.x;
    float* row = out + (size_t)n * DIM;
    const float* xr = X + (size_t)n * DIM;
    int tid = threadIdx.x;

    float v0 = row[tid]       + xr[tid];
    float v1 = row[tid + 256] + xr[tid + 256];
    float v2 = row[tid + 512] + xr[tid + 512];
    float s = v0 + v1 + v2;
    float s2 = v0 * v0 + v1 * v1 + v2 * v2;
#pragma unroll
    for (int o = 16; o > 0; o >>= 1) {
        s  += __shfl_xor_sync(0xffffffffu, s, o);
        s2 += __shfl_xor_sync(0xffffffffu, s2, o);
    }
    int w = tid >> 5, l = tid & 31;
    if (l == 0) { red[w] = s; red[8 + w] = s2; }
    __syncthreads();
    if (w == 0) {
        float a = (l < 8) ? red[l] : 0.f;
        float b = (l < 8) ? red[8 + l] : 0.f;
#pragma unroll
        for (int o = 4; o > 0; o >>= 1) {
            a += __shfl_xor_sync(0xffffffffu, a, o);
            b += __shfl_xor_sync(0xffffffffu, b, o);
        }
        if (l == 0) { red[32] = a; red[33] = b; }
    }
    __syncthreads();
    float mu = red[32] * (1.0f / DIM);
    float var = red[33] * (1.0f / DIM) - mu * mu;
    float inv = rsqrtf(var + LN_EPS);
    row[tid]       = (v0 - mu) * inv * gamma[tid]       + beta[tid];
    row[tid + 256] = (v1 - mu) * inv * gamma[tid + 256] + beta[tid + 256];
    row[tid + 512] = (v2 - mu) * inv * gamma[tid + 512] + beta[tid + 512];
}

// ---------------------------------------------------------------------------
// kernel_launch
// ---------------------------------------------------------------------------
extern "C" void kernel_launch(void* const* d_in, const int* in_sizes, int n_in,
                              void* d_out, int out_size) {
    const float* X   = (const float*)d_in[0];
    const float* Wm  = (const float*)d_in[1];
    const float* bm  = (const float*)d_in[2];
    const float* Wu  = (const float*)d_in[3];
    const float* bu  = (const float*)d_in[4];
    const float* gam = (const float*)d_in[5];
    const float* bet = (const float*)d_in[6];
    const int*   eidx= (const int*)d_in[7];
    const int*   etyp= (const int*)d_in[8];
    float* out = (float*)d_out;

    (void)in_sizes; (void)n_in; (void)out_size;

    cudaFuncSetAttribute(k_msg, cudaFuncAttributeMaxDynamicSharedMemorySize, SMEM_SZ);
    cudaFuncSetAttribute(k_upd, cudaFuncAttributeMaxDynamicSharedMemorySize, SMEM_SZ);

    void* xtf;  cudaGetSymbolAddress(&xtf,  g_xtf_v);
    void* wmtf; cudaGetSymbolAddress(&wmtf, g_wmtf_v);
    void* wutf; cudaGetSymbolAddress(&wutf, g_wutf_v);

    k_init<<<4096, 256>>>();
    k_bucket<<<(NE + 255) / 256, 256>>>(etyp);

    // f32 -> fp16(rn) + K-permute all inputs in one launch
    k_cvtp3<<<4096, 256>>>(X,  (__half*)xtf,  (size_t)NN * DIM / 32,
                           Wm, (__half*)wmtf, (size_t)NT * DIM * DIM / 32,
                           Wu, (__half*)wutf, (size_t)DIM * DIM2 / 32);

    dim3 gm(DIM / BN, (NE + BM - 1) / BM, NT);
    k_msg<<<gm, THREADS, SMEM_SZ>>>(bm, eidx);

    dim3 gu(DIM / BN, (NN + BM - 1) / BM);
    k_upd<<<gu, THREADS, SMEM_SZ>>>(bu, out);

    k_ln<<<NN, 256>>>(out, X, gam, bet);
}